// round 15
// baseline (speedup 1.0000x reference)
#include <cuda_runtime.h>
#include <cuda_fp16.h>
#include <cstdint>

#define XP 136
#define AP 136
#define CP 136
#define NB 3   // X buffer stages

struct Sm {
    __half xhi[NB][128 * XP];
    __half chi[32 * CP];
    __half ahi[32 * AP];
    float x2[NB][128];
    float x2p[1024];
    float Spart[8 * 32];
    float c2[32], scl[32];
};

static __device__ __forceinline__ uint32_t sptr(const void* p) {
    return (uint32_t)__cvta_generic_to_shared(p);
}
static __device__ __forceinline__ void ldsm4(uint32_t* r, uint32_t a) {
    asm volatile("ldmatrix.sync.aligned.m8n8.x4.shared.b16 {%0,%1,%2,%3},[%4];"
                 : "=r"(r[0]), "=r"(r[1]), "=r"(r[2]), "=r"(r[3]) : "r"(a));
}
static __device__ __forceinline__ void ldsm4t(uint32_t* r, uint32_t a) {
    asm volatile("ldmatrix.sync.aligned.m8n8.x4.trans.shared.b16 {%0,%1,%2,%3},[%4];"
                 : "=r"(r[0]), "=r"(r[1]), "=r"(r[2]), "=r"(r[3]) : "r"(a));
}
static __device__ __forceinline__ void mma16816(float* c, const uint32_t* a, const uint32_t* b) {
    asm volatile(
        "mma.sync.aligned.m16n8k16.row.col.f32.f16.f16.f32 "
        "{%0,%1,%2,%3},{%4,%5,%6,%7},{%8,%9},{%0,%1,%2,%3};"
        : "+f"(c[0]), "+f"(c[1]), "+f"(c[2]), "+f"(c[3])
        : "r"(a[0]), "r"(a[1]), "r"(a[2]), "r"(a[3]), "r"(b[0]), "r"(b[1]));
}
static __device__ __forceinline__ void barsync(int id, int cnt) {
    asm volatile("bar.sync %0, %1;" :: "r"(id), "r"(cnt) : "memory");
}
static __device__ __forceinline__ void bararrive(int id, int cnt) {
    asm volatile("bar.arrive %0, %1;" :: "r"(id), "r"(cnt) : "memory");
}

// bars: EMPTY b = 1+b (512), heavy internal = 4 (256), FULL b = 5+b (512), prod internal = 9 (256)

__global__ void __launch_bounds__(512, 1)
enc_kernel(const float* __restrict__ X, const float* __restrict__ Cg,
           const float* __restrict__ scaleg, float* __restrict__ out)
{
    extern __shared__ char raw[];
    Sm& s = *reinterpret_cast<Sm*>(raw);
    const int tid = threadIdx.x, lane = tid & 31, w = tid >> 5;

    for (int i = tid; i < 4096; i += 512) {
        int k = i >> 7, d = i & 127;
        s.chi[k * CP + d] = __float2half(Cg[i]);
    }
    if (tid < 32) {
        float c2 = 0.f;
        #pragma unroll 8
        for (int d = 0; d < 128; d++) { float c = Cg[tid * 128 + d]; c2 += c * c; }
        s.c2[tid] = c2;
        s.scl[tid] = scaleg[tid];
    }
    __syncthreads();

    const int nq = (1024 - (int)blockIdx.x + (int)gridDim.x - 1) / (int)gridDim.x;
    const int TL = nq * 4;

    if (w < 8) {
        // ===== PRODUCER (warps 0-7): whole-tile register preload, 3-stage =====
        const int nl = lane * 4;
        float4 va[16];
        {
            const int u = blockIdx.x;
            const float* base = X + (size_t)(u >> 5) * (128 * 16384) + (u & 31) * 512 + nl;
            #pragma unroll
            for (int i = 0; i < 16; i++)
                va[i] = *reinterpret_cast<const float4*>(base + (size_t)(w * 16 + i) * 16384);
        }
        int bi = 0;
        for (int tl = 0; tl < TL; tl++) {
            barsync(1 + bi, 512);              // wait buffer empty (rarely blocks, 3 stages)
            __half* xh = s.xhi[bi];
            float p0 = 0.f, p1 = 0.f, p2 = 0.f, p3 = 0.f;
            #pragma unroll
            for (int i = 0; i < 16; i++) {
                const int d = w * 16 + i;
                const float4 v = va[i];
                __half2 H0 = __floats2half2_rn(v.x, v.y);
                __half2 H1 = __floats2half2_rn(v.z, v.w);
                *reinterpret_cast<__half2*>(&xh[d * XP + nl])     = H0;
                *reinterpret_cast<__half2*>(&xh[d * XP + nl + 2]) = H1;
                p0 = fmaf(v.x, v.x, p0); p1 = fmaf(v.y, v.y, p1);
                p2 = fmaf(v.z, v.z, p2); p3 = fmaf(v.w, v.w, p3);
            }
            *reinterpret_cast<float4*>(&s.x2p[w * 128 + nl]) = make_float4(p0, p1, p2, p3);
            barsync(9, 256);
            if (tid < 128) {
                float sum = 0.f;
                #pragma unroll
                for (int q = 0; q < 8; q++) sum += s.x2p[q * 128 + tid];
                s.x2[bi][tid] = sum;
            }
            __threadfence_block();
            bararrive(5 + bi, 512);            // signal buffer full
            // preload next tile entirely into registers — latency hidden by consumers
            if (tl + 1 < TL) {
                const int u2 = blockIdx.x + ((tl + 1) >> 2) * gridDim.x;
                const float* b2 = X + (size_t)(u2 >> 5) * (128 * 16384)
                                + (u2 & 31) * 512 + ((tl + 1) & 3) * 128 + nl;
                #pragma unroll
                for (int i = 0; i < 16; i++)
                    va[i] = *reinterpret_cast<const float4*>(b2 + (size_t)(w * 16 + i) * 16384);
            }
            bi = (bi == NB - 1) ? 0 : bi + 1;
        }
    } else {
        // ================= HEAVY (warps 8-15) =================
        const int hw = w - 8;
        const int g = lane >> 2, t = lane & 3;
        const int lr = lane & 15, lh = lane >> 4;
        const int brow = (lane >> 4) * 8 + (lane & 7);
        const int bcol = ((lane >> 3) & 1) * 8;
        const int nb = hw * 16;
        const float sc0 = s.scl[g],      cc0 = s.c2[g];
        const float sc1 = s.scl[g + 8],  cc1 = s.c2[g + 8];
        const float sc2 = s.scl[g + 16], cc2 = s.c2[g + 16];
        const float sc3 = s.scl[g + 24], cc3 = s.c2[g + 24];

        // partial C-fragment hoist (kd 0..3)
        uint32_t cfr[4][2][4];
        #pragma unroll
        for (int kd = 0; kd < 4; kd++) {
            ldsm4(cfr[kd][0], sptr(&s.chi[lr * CP + kd * 16 + lh * 8]));
            ldsm4(cfr[kd][1], sptr(&s.chi[(16 + lr) * CP + kd * 16 + lh * 8]));
        }
        bararrive(1, 512);                     // prime all EMPTY stages
        bararrive(2, 512);
        bararrive(3, 512);

        float e[4][4];
        #pragma unroll
        for (int j = 0; j < 4; j++) { e[j][0] = 0.f; e[j][1] = 0.f; e[j][2] = 0.f; e[j][3] = 0.f; }
        float Sr[4] = {0.f, 0.f, 0.f, 0.f};
        int bi = 0;

        for (int tl = 0; tl < TL; tl++) {
            const int u = blockIdx.x + (tl >> 2) * gridDim.x;
            barsync(5 + bi, 512);              // wait buffer full
            const __half* xh = s.xhi[bi];

            // ---- GEMM1 ----
            float acc[2][2][4];
            #pragma unroll
            for (int mt = 0; mt < 2; mt++)
                #pragma unroll
                for (int nt = 0; nt < 2; nt++) {
                    acc[mt][nt][0] = 0.f; acc[mt][nt][1] = 0.f;
                    acc[mt][nt][2] = 0.f; acc[mt][nt][3] = 0.f;
                }
            #pragma unroll
            for (int kd = 0; kd < 4; kd++) {
                uint32_t bh[4];
                ldsm4t(bh, sptr(&xh[(kd * 16 + lr) * XP + nb + lh * 8]));
                mma16816(acc[0][0], cfr[kd][0], bh + 0);
                mma16816(acc[0][1], cfr[kd][0], bh + 2);
                mma16816(acc[1][0], cfr[kd][1], bh + 0);
                mma16816(acc[1][1], cfr[kd][1], bh + 2);
            }
            #pragma unroll
            for (int kd = 4; kd < 8; kd++) {
                uint32_t a0[4], a1[4], bh[4];
                ldsm4(a0, sptr(&s.chi[lr * CP + kd * 16 + lh * 8]));
                ldsm4(a1, sptr(&s.chi[(16 + lr) * CP + kd * 16 + lh * 8]));
                ldsm4t(bh, sptr(&xh[(kd * 16 + lr) * XP + nb + lh * 8]));
                mma16816(acc[0][0], a0, bh + 0);
                mma16816(acc[0][1], a0, bh + 2);
                mma16816(acc[1][0], a1, bh + 0);
                mma16816(acc[1][1], a1, bh + 2);
            }

            // ---- in-register softmax ----
            const float* x2 = s.x2[bi];
            float sl[4][4], m[4], sum[4];
            #pragma unroll
            for (int j = 0; j < 4; j++) {
                const int nt = j >> 1, jc = j & 1;
                const float xv = x2[nb + nt * 8 + 2 * t + jc];
                sl[j][0] = sc0 * (xv - 2.f * acc[0][nt][jc]     + cc0);
                sl[j][1] = sc1 * (xv - 2.f * acc[0][nt][jc + 2] + cc1);
                sl[j][2] = sc2 * (xv - 2.f * acc[1][nt][jc]     + cc2);
                sl[j][3] = sc3 * (xv - 2.f * acc[1][nt][jc + 2] + cc3);
                m[j] = fmaxf(fmaxf(sl[j][0], sl[j][1]), fmaxf(sl[j][2], sl[j][3]));
            }
            #pragma unroll
            for (int j = 0; j < 4; j++) {
                m[j] = fmaxf(m[j], __shfl_xor_sync(0xffffffffu, m[j], 4));
                m[j] = fmaxf(m[j], __shfl_xor_sync(0xffffffffu, m[j], 8));
                m[j] = fmaxf(m[j], __shfl_xor_sync(0xffffffffu, m[j], 16));
                sl[j][0] = __expf(sl[j][0] - m[j]); sl[j][1] = __expf(sl[j][1] - m[j]);
                sl[j][2] = __expf(sl[j][2] - m[j]); sl[j][3] = __expf(sl[j][3] - m[j]);
                sum[j] = sl[j][0] + sl[j][1] + sl[j][2] + sl[j][3];
                sum[j] += __shfl_xor_sync(0xffffffffu, sum[j], 4);
                sum[j] += __shfl_xor_sync(0xffffffffu, sum[j], 8);
                sum[j] += __shfl_xor_sync(0xffffffffu, sum[j], 16);
                const float f = 1.f / sum[j];
                sl[j][0] *= f; sl[j][1] *= f; sl[j][2] *= f; sl[j][3] *= f;
                Sr[0] += sl[j][0]; Sr[1] += sl[j][1];
                Sr[2] += sl[j][2]; Sr[3] += sl[j][3];
            }
            // ---- A write ----
            #pragma unroll
            for (int i = 0; i < 4; i++) {
                const int k = (i < 2) ? (g + 8 * i) : (16 + g + 8 * (i - 2));
                #pragma unroll
                for (int jp = 0; jp < 2; jp++) {
                    __half2 H = __floats2half2_rn(sl[jp * 2 + 0][i], sl[jp * 2 + 1][i]);
                    *reinterpret_cast<__half2*>(&s.ahi[k * AP + nb + jp * 8 + 2 * t]) = H;
                }
            }
            barsync(4, 256);   // A complete

            // ---- GEMM2 ----
            #pragma unroll
            for (int kn = 0; kn < 8; kn++) {
                const int nn = kn * 16;
                uint32_t Xh[4];
                ldsm4(Xh, sptr(&xh[(16 * hw + lr) * XP + nn + lh * 8]));
                uint32_t b0h[4], b1h[4];
                ldsm4(b0h, sptr(&s.ahi[brow * AP + nn + bcol]));
                ldsm4(b1h, sptr(&s.ahi[(16 + brow) * AP + nn + bcol]));
                mma16816(e[0], Xh, b0h + 0);
                mma16816(e[1], Xh, b0h + 2);
                mma16816(e[2], Xh, b1h + 0);
                mma16816(e[3], Xh, b1h + 2);
            }
            bararrive(1 + bi, 512);            // signal buffer empty

            // ---- unit epilogue ----
            if ((tl & 3) == 3) {
                #pragma unroll
                for (int i = 0; i < 4; i++) {
                    Sr[i] += __shfl_xor_sync(0xffffffffu, Sr[i], 1);
                    Sr[i] += __shfl_xor_sync(0xffffffffu, Sr[i], 2);
                }
                if (t == 0) {
                    s.Spart[hw * 32 + g]      = Sr[0];
                    s.Spart[hw * 32 + g + 8]  = Sr[1];
                    s.Spart[hw * 32 + g + 16] = Sr[2];
                    s.Spart[hw * 32 + g + 24] = Sr[3];
                }
                Sr[0] = 0.f; Sr[1] = 0.f; Sr[2] = 0.f; Sr[3] = 0.f;
                barsync(4, 256);
                float* outb = out + (size_t)(u >> 5) * 4096;
                #pragma unroll
                for (int j = 0; j < 4; j++) {
                    const int k0 = j * 8 + 2 * t, d0 = 16 * hw + g;
                    float S0 = 0.f, S1 = 0.f;
                    #pragma unroll
                    for (int q = 0; q < 8; q++) {
                        S0 += s.Spart[q * 32 + k0];
                        S1 += s.Spart[q * 32 + k0 + 1];
                    }
                    atomicAdd(&outb[k0 * 128 + d0],            e[j][0] - S0 * Cg[k0 * 128 + d0]);
                    atomicAdd(&outb[(k0 + 1) * 128 + d0],      e[j][1] - S1 * Cg[(k0 + 1) * 128 + d0]);
                    atomicAdd(&outb[k0 * 128 + d0 + 8],        e[j][2] - S0 * Cg[k0 * 128 + d0 + 8]);
                    atomicAdd(&outb[(k0 + 1) * 128 + d0 + 8],  e[j][3] - S1 * Cg[(k0 + 1) * 128 + d0 + 8]);
                    e[j][0] = 0.f; e[j][1] = 0.f; e[j][2] = 0.f; e[j][3] = 0.f;
                }
            }
            bi = (bi == NB - 1) ? 0 : bi + 1;
        }
    }
}

extern "C" void kernel_launch(void* const* d_in, const int* in_sizes, int n_in,
                              void* d_out, int out_size) {
    const float* X  = (const float*)d_in[0];
    const float* C  = (const float*)d_in[1];
    const float* sc = (const float*)d_in[2];
    float* out = (float*)d_out;

    int dev = 0, sms = 0;
    cudaGetDevice(&dev);
    cudaDeviceGetAttribute(&sms, cudaDevAttrMultiProcessorCount, dev);
    if (sms <= 0) sms = 148;

    cudaFuncSetAttribute(enc_kernel, cudaFuncAttributeMaxDynamicSharedMemorySize,
                         (int)sizeof(Sm));
    cudaMemsetAsync(out, 0, (size_t)out_size * sizeof(float));
    enc_kernel<<<sms, 512, sizeof(Sm)>>>(X, C, sc, out);
}

// round 16
// speedup vs baseline: 1.0248x; 1.0248x over previous
#include <cuda_runtime.h>
#include <cuda_fp16.h>
#include <cstdint>

#define XP 136
#define AP 136
#define CP 136

struct Sm {
    __half xhi[3][128 * XP];
    __half chi[32 * CP];
    __half ahi[2][32 * AP];
    float x2[3][128];
    float x2p[512];
    float Spart[8 * 32];
    float c2[32], scl[32];
};

static __device__ __forceinline__ uint32_t sptr(const void* p) {
    return (uint32_t)__cvta_generic_to_shared(p);
}
static __device__ __forceinline__ void ldsm4(uint32_t* r, uint32_t a) {
    asm volatile("ldmatrix.sync.aligned.m8n8.x4.shared.b16 {%0,%1,%2,%3},[%4];"
                 : "=r"(r[0]), "=r"(r[1]), "=r"(r[2]), "=r"(r[3]) : "r"(a));
}
static __device__ __forceinline__ void ldsm4t(uint32_t* r, uint32_t a) {
    asm volatile("ldmatrix.sync.aligned.m8n8.x4.trans.shared.b16 {%0,%1,%2,%3},[%4];"
                 : "=r"(r[0]), "=r"(r[1]), "=r"(r[2]), "=r"(r[3]) : "r"(a));
}
static __device__ __forceinline__ void mma16816(float* c, const uint32_t* a, const uint32_t* b) {
    asm volatile(
        "mma.sync.aligned.m16n8k16.row.col.f32.f16.f16.f32 "
        "{%0,%1,%2,%3},{%4,%5,%6,%7},{%8,%9},{%0,%1,%2,%3};"
        : "+f"(c[0]), "+f"(c[1]), "+f"(c[2]), "+f"(c[3])
        : "r"(a[0]), "r"(a[1]), "r"(a[2]), "r"(a[3]), "r"(b[0]), "r"(b[1]));
}
static __device__ __forceinline__ void barsync(int id, int cnt) {
    asm volatile("bar.sync %0, %1;" :: "r"(id), "r"(cnt) : "memory");
}
static __device__ __forceinline__ void bararrive(int id, int cnt) {
    asm volatile("bar.arrive %0, %1;" :: "r"(id), "r"(cnt) : "memory");
}

// bars: EMPTY s = 1+s (384), heavy=4 (256), FULL s = 5+s (384), prod=9 (128)

__global__ void __launch_bounds__(384, 1)
enc_kernel(const float* __restrict__ X, const float* __restrict__ Cg,
           const float* __restrict__ scaleg, float* __restrict__ out)
{
    extern __shared__ char raw[];
    Sm& s = *reinterpret_cast<Sm*>(raw);
    const int tid = threadIdx.x, lane = tid & 31, w = tid >> 5;

    for (int i = tid; i < 4096; i += 384) {
        int k = i >> 7, d = i & 127;
        s.chi[k * CP + d] = __float2half(Cg[i]);
    }
    if (tid < 32) {
        float c2 = 0.f;
        #pragma unroll 8
        for (int d = 0; d < 128; d++) { float c = Cg[tid * 128 + d]; c2 += c * c; }
        s.c2[tid] = c2;
        s.scl[tid] = scaleg[tid];
    }
    __syncthreads();

    const int nq = (1024 - (int)blockIdx.x + (int)gridDim.x - 1) / (int)gridDim.x;
    const int TL = nq * 4;

    if (w < 4) {
        // ===== PRODUCER (warps 0-3): R13-style pipelined, 3-stage buffers =====
        const int nl = lane * 4;
        float4 va[16];
        {
            const int u = blockIdx.x;
            const float* base = X + (size_t)(u >> 5) * (128 * 16384) + (u & 31) * 512 + nl;
            #pragma unroll
            for (int i = 0; i < 16; i++)
                va[i] = *reinterpret_cast<const float4*>(base + (size_t)(w * 32 + i) * 16384);
        }
        int bi = 0;
        for (int tl = 0; tl < TL; tl++) {
            const int u = blockIdx.x + (tl >> 2) * gridDim.x;
            const float* base = X + (size_t)(u >> 5) * (128 * 16384)
                              + (u & 31) * 512 + (tl & 3) * 128 + nl;
            barsync(1 + bi, 384);
            float4 vb[16];
            #pragma unroll
            for (int i = 0; i < 16; i++)
                vb[i] = *reinterpret_cast<const float4*>(base + (size_t)(w * 32 + 16 + i) * 16384);
            __half* xh = s.xhi[bi];
            float p0 = 0.f, p1 = 0.f, p2 = 0.f, p3 = 0.f;
            #pragma unroll
            for (int i = 0; i < 16; i++) {
                const int d = w * 32 + i;
                const float4 v = va[i];
                __half2 H0 = __floats2half2_rn(v.x, v.y);
                __half2 H1 = __floats2half2_rn(v.z, v.w);
                *reinterpret_cast<__half2*>(&xh[d * XP + nl])     = H0;
                *reinterpret_cast<__half2*>(&xh[d * XP + nl + 2]) = H1;
                p0 = fmaf(v.x, v.x, p0); p1 = fmaf(v.y, v.y, p1);
                p2 = fmaf(v.z, v.z, p2); p3 = fmaf(v.w, v.w, p3);
            }
            #pragma unroll
            for (int i = 0; i < 16; i++) {
                const int d = w * 32 + 16 + i;
                const float4 v = vb[i];
                __half2 H0 = __floats2half2_rn(v.x, v.y);
                __half2 H1 = __floats2half2_rn(v.z, v.w);
                *reinterpret_cast<__half2*>(&xh[d * XP + nl])     = H0;
                *reinterpret_cast<__half2*>(&xh[d * XP + nl + 2]) = H1;
                p0 = fmaf(v.x, v.x, p0); p1 = fmaf(v.y, v.y, p1);
                p2 = fmaf(v.z, v.z, p2); p3 = fmaf(v.w, v.w, p3);
            }
            *reinterpret_cast<float4*>(&s.x2p[w * 128 + nl]) = make_float4(p0, p1, p2, p3);
            barsync(9, 128);
            s.x2[bi][tid] = s.x2p[tid] + s.x2p[128 + tid] + s.x2p[256 + tid] + s.x2p[384 + tid];
            __threadfence_block();
            bararrive(5 + bi, 384);
            if (tl + 1 < TL) {
                const int u2 = blockIdx.x + ((tl + 1) >> 2) * gridDim.x;
                const float* b2 = X + (size_t)(u2 >> 5) * (128 * 16384)
                                + (u2 & 31) * 512 + ((tl + 1) & 3) * 128 + nl;
                #pragma unroll
                for (int i = 0; i < 16; i++)
                    va[i] = *reinterpret_cast<const float4*>(b2 + (size_t)(w * 32 + i) * 16384);
            }
            bi = (bi == 2) ? 0 : bi + 1;
        }
    } else {
        // ================= HEAVY (warps 4-11), GEMM2 lagged by one subtile =================
        const int hw = w - 4;
        const int g = lane >> 2, t = lane & 3;
        const int lr = lane & 15, lh = lane >> 4;
        const int brow = (lane >> 4) * 8 + (lane & 7);
        const int bcol = ((lane >> 3) & 1) * 8;
        const int nb = hw * 16;
        const float sc0 = s.scl[g],      cc0 = s.c2[g];
        const float sc1 = s.scl[g + 8],  cc1 = s.c2[g + 8];
        const float sc2 = s.scl[g + 16], cc2 = s.c2[g + 16];
        const float sc3 = s.scl[g + 24], cc3 = s.c2[g + 24];

        uint32_t cfr[8][2][4];
        #pragma unroll
        for (int kd = 0; kd < 8; kd++) {
            ldsm4(cfr[kd][0], sptr(&s.chi[lr * CP + kd * 16 + lh * 8]));
            ldsm4(cfr[kd][1], sptr(&s.chi[(16 + lr) * CP + kd * 16 + lh * 8]));
        }
        bararrive(1, 384); bararrive(2, 384); bararrive(3, 384);

        float e[4][4];
        #pragma unroll
        for (int j = 0; j < 4; j++) { e[j][0] = 0.f; e[j][1] = 0.f; e[j][2] = 0.f; e[j][3] = 0.f; }
        float Sr[4] = {0.f, 0.f, 0.f, 0.f};
        int pa = 0;

        for (int tl = 0; tl < TL; tl++) {
            const int bi = tl % 3;
            const int prev = (tl + 2) % 3;
            barsync(5 + bi, 384);
            const __half* xh = s.xhi[bi];
            const __half* xp = s.xhi[prev];
            const __half* ap = s.ahi[pa ^ 1];
            const bool lag = (tl > 0);

            // ---- fused: GEMM1(tl) + GEMM2(tl-1) ----
            float acc[2][2][4];
            #pragma unroll
            for (int mt = 0; mt < 2; mt++)
                #pragma unroll
                for (int nt = 0; nt < 2; nt++) {
                    acc[mt][nt][0] = 0.f; acc[mt][nt][1] = 0.f;
                    acc[mt][nt][2] = 0.f; acc[mt][nt][3] = 0.f;
                }
            #pragma unroll
            for (int kd = 0; kd < 8; kd++) {
                uint32_t bh[4];
                ldsm4t(bh, sptr(&xh[(kd * 16 + lr) * XP + nb + lh * 8]));
                if (lag) {
                    const int nn = kd * 16;
                    uint32_t Xh[4], b0h[4], b1h[4];
                    ldsm4(Xh, sptr(&xp[(16 * hw + lr) * XP + nn + lh * 8]));
                    ldsm4(b0h, sptr(&ap[brow * AP + nn + bcol]));
                    ldsm4(b1h, sptr(&ap[(16 + brow) * AP + nn + bcol]));
                    mma16816(e[0], Xh, b0h + 0);
                    mma16816(e[1], Xh, b0h + 2);
                    mma16816(e[2], Xh, b1h + 0);
                    mma16816(e[3], Xh, b1h + 2);
                }
                mma16816(acc[0][0], cfr[kd][0], bh + 0);
                mma16816(acc[0][1], cfr[kd][0], bh + 2);
                mma16816(acc[1][0], cfr[kd][1], bh + 0);
                mma16816(acc[1][1], cfr[kd][1], bh + 2);
            }
            if (lag) {
                bararrive(1 + prev, 384);          // buffer tl-1 free
                if ((tl & 3) == 0) {               // flush unit (tl>>2)-1
                    const int uf = blockIdx.x + ((tl >> 2) - 1) * gridDim.x;
                    float* outb = out + (size_t)(uf >> 5) * 4096;
                    #pragma unroll
                    for (int j = 0; j < 4; j++) {
                        const int k0 = j * 8 + 2 * t, d0 = 16 * hw + g;
                        float S0 = 0.f, S1 = 0.f;
                        #pragma unroll
                        for (int q = 0; q < 8; q++) {
                            S0 += s.Spart[q * 32 + k0];
                            S1 += s.Spart[q * 32 + k0 + 1];
                        }
                        atomicAdd(&outb[k0 * 128 + d0],           e[j][0] - S0 * Cg[k0 * 128 + d0]);
                        atomicAdd(&outb[(k0 + 1) * 128 + d0],     e[j][1] - S1 * Cg[(k0 + 1) * 128 + d0]);
                        atomicAdd(&outb[k0 * 128 + d0 + 8],       e[j][2] - S0 * Cg[k0 * 128 + d0 + 8]);
                        atomicAdd(&outb[(k0 + 1) * 128 + d0 + 8], e[j][3] - S1 * Cg[(k0 + 1) * 128 + d0 + 8]);
                        e[j][0] = 0.f; e[j][1] = 0.f; e[j][2] = 0.f; e[j][3] = 0.f;
                    }
                }
            }

            // ---- in-register softmax(tl) ----
            const float* x2 = s.x2[bi];
            float sl[4][4], m[4], sum[4];
            #pragma unroll
            for (int j = 0; j < 4; j++) {
                const int nt = j >> 1, jc = j & 1;
                const float xv = x2[nb + nt * 8 + 2 * t + jc];
                sl[j][0] = sc0 * (xv - 2.f * acc[0][nt][jc]     + cc0);
                sl[j][1] = sc1 * (xv - 2.f * acc[0][nt][jc + 2] + cc1);
                sl[j][2] = sc2 * (xv - 2.f * acc[1][nt][jc]     + cc2);
                sl[j][3] = sc3 * (xv - 2.f * acc[1][nt][jc + 2] + cc3);
                m[j] = fmaxf(fmaxf(sl[j][0], sl[j][1]), fmaxf(sl[j][2], sl[j][3]));
            }
            #pragma unroll
            for (int j = 0; j < 4; j++) {
                m[j] = fmaxf(m[j], __shfl_xor_sync(0xffffffffu, m[j], 4));
                m[j] = fmaxf(m[j], __shfl_xor_sync(0xffffffffu, m[j], 8));
                m[j] = fmaxf(m[j], __shfl_xor_sync(0xffffffffu, m[j], 16));
                sl[j][0] = __expf(sl[j][0] - m[j]); sl[j][1] = __expf(sl[j][1] - m[j]);
                sl[j][2] = __expf(sl[j][2] - m[j]); sl[j][3] = __expf(sl[j][3] - m[j]);
                sum[j] = sl[j][0] + sl[j][1] + sl[j][2] + sl[j][3];
                sum[j] += __shfl_xor_sync(0xffffffffu, sum[j], 4);
                sum[j] += __shfl_xor_sync(0xffffffffu, sum[j], 8);
                sum[j] += __shfl_xor_sync(0xffffffffu, sum[j], 16);
                const float f = 1.f / sum[j];
                sl[j][0] *= f; sl[j][1] *= f; sl[j][2] *= f; sl[j][3] *= f;
                Sr[0] += sl[j][0]; Sr[1] += sl[j][1];
                Sr[2] += sl[j][2]; Sr[3] += sl[j][3];
            }
            // ---- A(tl) write into ahi[pa] ----
            __half* ac = s.ahi[pa];
            #pragma unroll
            for (int i = 0; i < 4; i++) {
                const int k = (i < 2) ? (g + 8 * i) : (16 + g + 8 * (i - 2));
                #pragma unroll
                for (int jp = 0; jp < 2; jp++) {
                    __half2 H = __floats2half2_rn(sl[jp * 2 + 0][i], sl[jp * 2 + 1][i]);
                    *reinterpret_cast<__half2*>(&ac[k * AP + nb + jp * 8 + 2 * t]) = H;
                }
            }
            if ((tl & 3) == 3) {
                float r0 = Sr[0], r1 = Sr[1], r2 = Sr[2], r3 = Sr[3];
                #pragma unroll
                for (int o = 1; o <= 2; o <<= 1) {
                    r0 += __shfl_xor_sync(0xffffffffu, r0, o);
                    r1 += __shfl_xor_sync(0xffffffffu, r1, o);
                    r2 += __shfl_xor_sync(0xffffffffu, r2, o);
                    r3 += __shfl_xor_sync(0xffffffffu, r3, o);
                }
                if (t == 0) {
                    s.Spart[hw * 32 + g]      = r0;
                    s.Spart[hw * 32 + g + 8]  = r1;
                    s.Spart[hw * 32 + g + 16] = r2;
                    s.Spart[hw * 32 + g + 24] = r3;
                }
                Sr[0] = 0.f; Sr[1] = 0.f; Sr[2] = 0.f; Sr[3] = 0.f;
            }
            barsync(4, 256);   // A(tl) + Spart visible to all heavy warps
            pa ^= 1;
        }

        // ---- drain: GEMM2(TL-1) + final flush ----
        {
            const int prev = (TL + 2) % 3;
            const __half* xp = s.xhi[prev];
            const __half* ap = s.ahi[pa ^ 1];
            #pragma unroll
            for (int kn = 0; kn < 8; kn++) {
                const int nn = kn * 16;
                uint32_t Xh[4], b0h[4], b1h[4];
                ldsm4(Xh, sptr(&xp[(16 * hw + lr) * XP + nn + lh * 8]));
                ldsm4(b0h, sptr(&ap[brow * AP + nn + bcol]));
                ldsm4(b1h, sptr(&ap[(16 + brow) * AP + nn + bcol]));
                mma16816(e[0], Xh, b0h + 0);
                mma16816(e[1], Xh, b0h + 2);
                mma16816(e[2], Xh, b1h + 0);
                mma16816(e[3], Xh, b1h + 2);
            }
            const int uf = blockIdx.x + (nq - 1) * gridDim.x;
            float* outb = out + (size_t)(uf >> 5) * 4096;
            #pragma unroll
            for (int j = 0; j < 4; j++) {
                const int k0 = j * 8 + 2 * t, d0 = 16 * hw + g;
                float S0 = 0.f, S1 = 0.f;
                #pragma unroll
                for (int q = 0; q < 8; q++) {
                    S0 += s.Spart[q * 32 + k0];
                    S1 += s.Spart[q * 32 + k0 + 1];
                }
                atomicAdd(&outb[k0 * 128 + d0],           e[j][0] - S0 * Cg[k0 * 128 + d0]);
                atomicAdd(&outb[(k0 + 1) * 128 + d0],     e[j][1] - S1 * Cg[(k0 + 1) * 128 + d0]);
                atomicAdd(&outb[k0 * 128 + d0 + 8],       e[j][2] - S0 * Cg[k0 * 128 + d0 + 8]);
                atomicAdd(&outb[(k0 + 1) * 128 + d0 + 8], e[j][3] - S1 * Cg[(k0 + 1) * 128 + d0 + 8]);
            }
        }
    }
}

extern "C" void kernel_launch(void* const* d_in, const int* in_sizes, int n_in,
                              void* d_out, int out_size) {
    const float* X  = (const float*)d_in[0];
    const float* C  = (const float*)d_in[1];
    const float* sc = (const float*)d_in[2];
    float* out = (float*)d_out;

    int dev = 0, sms = 0;
    cudaGetDevice(&dev);
    cudaDeviceGetAttribute(&sms, cudaDevAttrMultiProcessorCount, dev);
    if (sms <= 0) sms = 148;

    cudaFuncSetAttribute(enc_kernel, cudaFuncAttributeMaxDynamicSharedMemorySize,
                         (int)sizeof(Sm));
    cudaMemsetAsync(out, 0, (size_t)out_size * sizeof(float));
    enc_kernel<<<sms, 384, sizeof(Sm)>>>(X, C, sc, out);
}